// round 2
// baseline (speedup 1.0000x reference)
#include <cuda_runtime.h>

#define N_NODES 20000
#define N_EDGES 320000
#define IN_CH   256
#define HID_CH  256
#define OUT_CH  128

// ---------------- scratch (device globals; no allocation) ----------------
__device__ float g_deg [N_NODES];
__device__ float g_dinv[N_NODES];
__device__ float g_y   [N_NODES * HID_CH];  // post-GEMM features (reused layer2)
__device__ float g_agg [N_NODES * HID_CH];  // scatter accumulator (layer1)
__device__ float g_h1  [N_NODES * HID_CH];  // layer1 output (post-ReLU)
__device__ int   g_is64;                    // edge_index dtype flag

// ---------------- edge dtype detection ----------------
// Scan first 2*N_EDGES 32-bit words (valid under both int32 and int64 layouts).
// int64 layout: words [0, 2E) are E little-endian int64 src indices; every odd
// word is the hi-word of a value in [0, 20000) -> 0. int32 layout: odd words
// are random indices, virtually certainly nonzero somewhere.
__global__ void k_init_flags() { g_is64 = 1; }

__global__ void k_detect(const unsigned int* __restrict__ w) {
    int i = blockIdx.x * blockDim.x + threadIdx.x;
    if (i < N_EDGES && w[2 * i + 1] != 0) g_is64 = 0;  // benign race
}

__device__ __forceinline__ int load_idx(const void* __restrict__ ei, int which, int e) {
    if (g_is64)
        return (int)((const long long*)ei)[(size_t)which * N_EDGES + e];
    return ((const int*)ei)[which * N_EDGES + e];
}

// ---------------- degree / normalization ----------------
__global__ void k_init_deg() {
    int i = blockIdx.x * blockDim.x + threadIdx.x;
    if (i < N_NODES) g_deg[i] = 1.0f;   // self-loop contributes 1
}

__global__ void k_count_deg(const void* __restrict__ ei) {
    int e = blockIdx.x * blockDim.x + threadIdx.x;
    if (e < N_EDGES) {
        int d = load_idx(ei, 1, e);
        atomicAdd(&g_deg[d], 1.0f);
    }
}

__global__ void k_dinv() {
    int i = blockIdx.x * blockDim.x + threadIdx.x;
    if (i < N_NODES) g_dinv[i] = rsqrtf(g_deg[i]);  // deg >= 1 always
}

// ---------------- zero helper ----------------
__global__ void k_zero(float* __restrict__ p, int n) {
    int i = blockIdx.x * blockDim.x + threadIdx.x;
    int stride = gridDim.x * blockDim.x;
    for (; i < n; i += stride) p[i] = 0.0f;
}

// ---------------- fp32 tiled GEMM: C[M,N] = A[M,K] @ B[K,N] ----------------
// BM=64, BN=64, BK=16, 256 threads, 4x4 microtile per thread.
__global__ void sgemm(const float* __restrict__ A, const float* __restrict__ B,
                      float* __restrict__ C, int M, int N, int K) {
    constexpr int BM = 64, BN = 64, BK = 16;
    __shared__ float As[BK][BM];
    __shared__ float Bs[BK][BN];

    int tid = threadIdx.x;
    int tx = tid & 15;
    int ty = tid >> 4;
    int rowBase = blockIdx.y * BM;
    int colBase = blockIdx.x * BN;

    float acc[4][4];
    #pragma unroll
    for (int i = 0; i < 4; i++)
        #pragma unroll
        for (int j = 0; j < 4; j++) acc[i][j] = 0.0f;

    for (int k0 = 0; k0 < K; k0 += BK) {
        int a_r = tid >> 2;
        int a_c = (tid & 3) << 2;
        float4 av = make_float4(0.f, 0.f, 0.f, 0.f);
        if (rowBase + a_r < M)
            av = *(const float4*)&A[(size_t)(rowBase + a_r) * K + k0 + a_c];
        As[a_c + 0][a_r] = av.x;
        As[a_c + 1][a_r] = av.y;
        As[a_c + 2][a_r] = av.z;
        As[a_c + 3][a_r] = av.w;

        int b_r = tid >> 4;
        int b_c = (tid & 15) << 2;
        float4 bv = *(const float4*)&B[(size_t)(k0 + b_r) * N + colBase + b_c];
        *(float4*)&Bs[b_r][b_c] = bv;

        __syncthreads();

        #pragma unroll
        for (int k = 0; k < BK; k++) {
            float4 a4 = *(const float4*)&As[k][ty << 2];
            float4 b4 = *(const float4*)&Bs[k][tx << 2];
            float ar[4] = {a4.x, a4.y, a4.z, a4.w};
            float br[4] = {b4.x, b4.y, b4.z, b4.w};
            #pragma unroll
            for (int i = 0; i < 4; i++)
                #pragma unroll
                for (int j = 0; j < 4; j++)
                    acc[i][j] += ar[i] * br[j];
        }
        __syncthreads();
    }

    #pragma unroll
    for (int i = 0; i < 4; i++) {
        int r = rowBase + (ty << 2) + i;
        if (r < M) {
            float4 o = make_float4(acc[i][0], acc[i][1], acc[i][2], acc[i][3]);
            *(float4*)&C[(size_t)r * N + colBase + (tx << 2)] = o;
        }
    }
}

// ---------------- edge scatter: agg[dst] += y[src] * dinv[src]*dinv[dst] ----------------
template <int CH>
__global__ void k_scatter(const void* __restrict__ ei,
                          const float* __restrict__ y,
                          float* __restrict__ agg) {
    constexpr int TPE = CH / 4;       // threads per edge (float4 per thread)
    constexpr int EPB = 256 / TPE;    // edges per 256-thread block
    int lane = threadIdx.x % TPE;
    int esub = threadIdx.x / TPE;
    int e = blockIdx.x * EPB + esub;
    if (e >= N_EDGES) return;

    int r = load_idx(ei, 0, e);
    int d = load_idx(ei, 1, e);
    float norm = g_dinv[r] * g_dinv[d];

    float4 v = *(const float4*)&y[(size_t)r * CH + lane * 4];
    float* o = &agg[(size_t)d * CH + lane * 4];
    atomicAdd(o + 0, v.x * norm);
    atomicAdd(o + 1, v.y * norm);
    atomicAdd(o + 2, v.z * norm);
    atomicAdd(o + 3, v.w * norm);
}

// ---------------- epilogue: out = agg + y*dinv^2 + b  (optional ReLU) ----------------
template <int CH, bool RELU>
__global__ void k_epilogue(const float* __restrict__ agg,
                           const float* __restrict__ y,
                           const float* __restrict__ b,
                           float* __restrict__ out) {
    int idx = blockIdx.x * blockDim.x + threadIdx.x;
    if (idx >= N_NODES * CH) return;
    int i = idx / CH;
    int c = idx - i * CH;
    float di = g_dinv[i];
    float v = agg[idx] + y[idx] * di * di + b[c];
    out[idx] = RELU ? fmaxf(v, 0.0f) : v;
}

// ---------------- launch ----------------
extern "C" void kernel_launch(void* const* d_in, const int* in_sizes, int n_in,
                              void* d_out, int out_size) {
    const float* x   = (const float*)d_in[0];
    const void*  ei  = d_in[1];
    const float* W1  = (const float*)d_in[2];
    const float* b1  = (const float*)d_in[3];
    const float* W2  = (const float*)d_in[4];
    const float* b2  = (const float*)d_in[5];
    float*       out = (float*)d_out;

    float *p_y, *p_agg, *p_h1;
    cudaGetSymbolAddress((void**)&p_y,   g_y);
    cudaGetSymbolAddress((void**)&p_agg, g_agg);
    cudaGetSymbolAddress((void**)&p_h1,  g_h1);

    // 0) detect edge_index dtype (int32 vs int64)
    k_init_flags<<<1, 1>>>();
    k_detect<<<(N_EDGES + 255) / 256, 256>>>((const unsigned int*)ei);

    // 1) degrees + dinv (shared by both layers)
    k_init_deg <<<(N_NODES + 255) / 256, 256>>>();
    k_count_deg<<<(N_EDGES + 255) / 256, 256>>>(ei);
    k_dinv     <<<(N_NODES + 255) / 256, 256>>>();

    // 2) layer 1: y = x @ W1
    {
        dim3 grid(HID_CH / 64, (N_NODES + 63) / 64);
        sgemm<<<grid, 256>>>(x, W1, p_y, N_NODES, HID_CH, IN_CH);
    }
    k_zero<<<2048, 256>>>(p_agg, N_NODES * HID_CH);
    {
        constexpr int EPB = 256 / (HID_CH / 4);  // 4 edges per block
        k_scatter<HID_CH><<<(N_EDGES + EPB - 1) / EPB, 256>>>(ei, p_y, p_agg);
    }
    k_epilogue<HID_CH, true><<<(N_NODES * HID_CH + 255) / 256, 256>>>(p_agg, p_y, b1, p_h1);

    // 3) layer 2: y = h1 @ W2, scatter directly into d_out
    {
        dim3 grid(OUT_CH / 64, (N_NODES + 63) / 64);
        sgemm<<<grid, 256>>>(p_h1, W2, p_y, N_NODES, OUT_CH, HID_CH);
    }
    k_zero<<<2048, 256>>>(out, N_NODES * OUT_CH);
    {
        constexpr int EPB = 256 / (OUT_CH / 4);  // 8 edges per block
        k_scatter<OUT_CH><<<(N_EDGES + EPB - 1) / EPB, 256>>>(ei, p_y, out);
    }
    k_epilogue<OUT_CH, false><<<(N_NODES * OUT_CH + 255) / 256, 256>>>(out, p_y, b2, out);
}

// round 3
// speedup vs baseline: 1.7282x; 1.7282x over previous
#include <cuda_runtime.h>

#define N_NODES 20000
#define N_EDGES 320000
#define IN_CH   256
#define HID_CH  256
#define OUT_CH  128

// ---------------- scratch (device globals; no allocation) ----------------
__device__ float g_dinv[N_NODES];
__device__ int   g_degi[N_NODES];
__device__ int   g_off [N_NODES + 1];
__device__ int   g_cur [N_NODES];
__device__ int   g_esrc[N_EDGES];
__device__ float g_enorm[N_EDGES];
__device__ float g_y   [N_NODES * HID_CH];  // post-GEMM features (reused layer2)
__device__ float g_h1  [N_NODES * HID_CH];  // layer1 output (post-ReLU)
__device__ int   g_is64;                    // edge_index dtype flag

// ---------------- edge dtype detection ----------------
__global__ void k_init_flags() { g_is64 = 1; }

__global__ void k_detect(const unsigned int* __restrict__ w) {
    int i = blockIdx.x * blockDim.x + threadIdx.x;
    if (i < N_EDGES && w[2 * i + 1] != 0) g_is64 = 0;  // benign race
}

__device__ __forceinline__ int load_idx(const void* __restrict__ ei, int which, int e) {
    if (g_is64)
        return (int)((const long long*)ei)[(size_t)which * N_EDGES + e];
    return ((const int*)ei)[which * N_EDGES + e];
}

// ---------------- CSR build ----------------
__global__ void k_zero_degi() {
    int i = blockIdx.x * blockDim.x + threadIdx.x;
    if (i < N_NODES) g_degi[i] = 0;
}

__global__ void k_hist(const void* __restrict__ ei) {
    int e = blockIdx.x * blockDim.x + threadIdx.x;
    if (e < N_EDGES) atomicAdd(&g_degi[load_idx(ei, 1, e)], 1);
}

// single-block exclusive scan over 20000 ints; also seeds cursor and dinv
__global__ void k_scan() {
    __shared__ int part[1024];
    int tid = threadIdx.x;
    const int per = (N_NODES + 1023) / 1024;   // 20
    int start = tid * per;
    int end   = min(start + per, N_NODES);
    int s = 0;
    for (int i = start; i < end; i++) s += g_degi[i];
    part[tid] = s;
    __syncthreads();
    for (int off = 1; off < 1024; off <<= 1) {
        int v = (tid >= off) ? part[tid - off] : 0;
        __syncthreads();
        part[tid] += v;
        __syncthreads();
    }
    int run = (tid > 0) ? part[tid - 1] : 0;
    for (int i = start; i < end; i++) {
        g_off[i] = run;
        g_cur[i] = run;
        run += g_degi[i];
        g_dinv[i] = rsqrtf((float)(g_degi[i] + 1));  // +1 self-loop
    }
    if (tid == 1023) g_off[N_NODES] = N_EDGES;
}

__global__ void k_fill(const void* __restrict__ ei) {
    int e = blockIdx.x * blockDim.x + threadIdx.x;
    if (e >= N_EDGES) return;
    int s = load_idx(ei, 0, e);
    int d = load_idx(ei, 1, e);
    int pos = atomicAdd(&g_cur[d], 1);
    g_esrc[pos]  = s;
    g_enorm[pos] = g_dinv[s] * g_dinv[d];
}

// ---------------- fp32 tiled GEMM: C[M,N] = A[M,K] @ B[K,N] ----------------
// BM=128, BN=128, BK=8, 256 threads, 8x8 microtile. N%128==0, K%8==0 required.
__global__ __launch_bounds__(256) void sgemm128(
        const float* __restrict__ A, const float* __restrict__ B,
        float* __restrict__ C, int M, int N, int K) {
    constexpr int BM = 128, BN = 128, BK = 8;
    __shared__ float As[BK][BM];
    __shared__ float Bs[BK][BN];

    int tid = threadIdx.x;
    int tx = tid & 15;        // 0..15 -> col microtile
    int ty = tid >> 4;        // 0..15 -> row microtile
    int rowBase = blockIdx.y * BM;
    int colBase = blockIdx.x * BN;

    float acc[8][8];
    #pragma unroll
    for (int i = 0; i < 8; i++)
        #pragma unroll
        for (int j = 0; j < 8; j++) acc[i][j] = 0.0f;

    // A-load mapping: 128 rows x 8 k; thread -> row=tid/2, k4=(tid&1)*4
    int a_r  = tid >> 1;
    int a_c4 = (tid & 1) << 2;
    // B-load mapping: 8 rows x 128 cols; thread -> row=tid/32, col4=(tid&31)*4
    int b_r  = tid >> 5;
    int b_c4 = (tid & 31) << 2;

    for (int k0 = 0; k0 < K; k0 += BK) {
        float4 av = make_float4(0.f, 0.f, 0.f, 0.f);
        if (rowBase + a_r < M)
            av = *(const float4*)&A[(size_t)(rowBase + a_r) * K + k0 + a_c4];
        As[a_c4 + 0][a_r] = av.x;
        As[a_c4 + 1][a_r] = av.y;
        As[a_c4 + 2][a_r] = av.z;
        As[a_c4 + 3][a_r] = av.w;

        float4 bv = *(const float4*)&B[(size_t)(k0 + b_r) * N + colBase + b_c4];
        *(float4*)&Bs[b_r][b_c4] = bv;

        __syncthreads();

        #pragma unroll
        for (int k = 0; k < BK; k++) {
            float ar[8], br[8];
            float4 a0 = *(const float4*)&As[k][ty * 8];
            float4 a1 = *(const float4*)&As[k][ty * 8 + 4];
            float4 b0 = *(const float4*)&Bs[k][tx * 8];
            float4 b1 = *(const float4*)&Bs[k][tx * 8 + 4];
            ar[0]=a0.x; ar[1]=a0.y; ar[2]=a0.z; ar[3]=a0.w;
            ar[4]=a1.x; ar[5]=a1.y; ar[6]=a1.z; ar[7]=a1.w;
            br[0]=b0.x; br[1]=b0.y; br[2]=b0.z; br[3]=b0.w;
            br[4]=b1.x; br[5]=b1.y; br[6]=b1.z; br[7]=b1.w;
            #pragma unroll
            for (int i = 0; i < 8; i++)
                #pragma unroll
                for (int j = 0; j < 8; j++)
                    acc[i][j] += ar[i] * br[j];
        }
        __syncthreads();
    }

    #pragma unroll
    for (int i = 0; i < 8; i++) {
        int r = rowBase + ty * 8 + i;
        if (r < M) {
            float4 o0 = make_float4(acc[i][0], acc[i][1], acc[i][2], acc[i][3]);
            float4 o1 = make_float4(acc[i][4], acc[i][5], acc[i][6], acc[i][7]);
            *(float4*)&C[(size_t)r * N + colBase + tx * 8]     = o0;
            *(float4*)&C[(size_t)r * N + colBase + tx * 8 + 4] = o1;
        }
    }
}

// ---------------- CSR gather + fused epilogue ----------------
// out[i] = sum_{e: dst=i} y[src_e]*norm_e + y[i]*dinv_i^2 + b   (optional ReLU)
template <int CH, bool RELU>
__global__ void k_gather(const float* __restrict__ y,
                         const float* __restrict__ b,
                         float* __restrict__ out) {
    constexpr int TPN = CH / 4;      // threads per node
    constexpr int NPB = 256 / TPN;   // nodes per block
    int lane = threadIdx.x % TPN;
    int node = blockIdx.x * NPB + threadIdx.x / TPN;
    if (node >= N_NODES) return;

    int beg = g_off[node];
    int end = g_off[node + 1];

    float4 acc = make_float4(0.f, 0.f, 0.f, 0.f);
    for (int p = beg; p < end; p++) {
        int   s   = g_esrc[p];
        float nrm = g_enorm[p];
        float4 v = *(const float4*)&y[(size_t)s * CH + lane * 4];
        acc.x += v.x * nrm; acc.y += v.y * nrm;
        acc.z += v.z * nrm; acc.w += v.w * nrm;
    }

    float di = g_dinv[node];
    float w  = di * di;
    float4 self = *(const float4*)&y[(size_t)node * CH + lane * 4];
    float4 bb   = *(const float4*)&b[lane * 4];
    acc.x += self.x * w + bb.x;
    acc.y += self.y * w + bb.y;
    acc.z += self.z * w + bb.z;
    acc.w += self.w * w + bb.w;
    if (RELU) {
        acc.x = fmaxf(acc.x, 0.f); acc.y = fmaxf(acc.y, 0.f);
        acc.z = fmaxf(acc.z, 0.f); acc.w = fmaxf(acc.w, 0.f);
    }
    *(float4*)&out[(size_t)node * CH + lane * 4] = acc;
}

// ---------------- launch ----------------
extern "C" void kernel_launch(void* const* d_in, const int* in_sizes, int n_in,
                              void* d_out, int out_size) {
    const float* x   = (const float*)d_in[0];
    const void*  ei  = d_in[1];
    const float* W1  = (const float*)d_in[2];
    const float* b1  = (const float*)d_in[3];
    const float* W2  = (const float*)d_in[4];
    const float* b2  = (const float*)d_in[5];
    float*       out = (float*)d_out;

    float *p_y, *p_h1;
    cudaGetSymbolAddress((void**)&p_y,  g_y);
    cudaGetSymbolAddress((void**)&p_h1, g_h1);

    // 0) dtype detection
    k_init_flags<<<1, 1>>>();
    k_detect<<<(N_EDGES + 255) / 256, 256>>>((const unsigned int*)ei);

    // 1) CSR build (+ dinv)
    k_zero_degi<<<(N_NODES + 255) / 256, 256>>>();
    k_hist<<<(N_EDGES + 255) / 256, 256>>>(ei);
    k_scan<<<1, 1024>>>();
    k_fill<<<(N_EDGES + 255) / 256, 256>>>(ei);

    // 2) layer 1: y = x @ W1 ; h1 = relu(gather(y) + self + b1)
    {
        dim3 grid(HID_CH / 128, (N_NODES + 127) / 128);
        sgemm128<<<grid, 256>>>(x, W1, p_y, N_NODES, HID_CH, IN_CH);
    }
    {
        constexpr int NPB = 256 / (HID_CH / 4);  // 4 nodes per block
        k_gather<HID_CH, true><<<(N_NODES + NPB - 1) / NPB, 256>>>(p_y, b1, p_h1);
    }

    // 3) layer 2: y = h1 @ W2 ; out = gather(y) + self + b2
    {
        dim3 grid(OUT_CH / 128, (N_NODES + 127) / 128);
        sgemm128<<<grid, 256>>>(p_h1, W2, p_y, N_NODES, OUT_CH, HID_CH);
    }
    {
        constexpr int NPB = 256 / (OUT_CH / 4);  // 8 nodes per block
        k_gather<OUT_CH, false><<<(N_NODES + NPB - 1) / NPB, 256>>>(p_y, b2, out);
    }
}

// round 5
// speedup vs baseline: 3.0160x; 1.7452x over previous
#include <cuda_runtime.h>
#include <cstdint>

#define N_NODES 20000
#define N_EDGES 320000
#define IN_CH   256
#define HID_CH  256
#define OUT_CH  128
#define KDIM    256

// ---------------- scratch (device globals; no allocation) ----------------
__device__ float g_dinv[N_NODES];
__device__ int   g_degi[N_NODES];
__device__ int   g_off [N_NODES + 1];
__device__ int   g_cur [N_NODES];
__device__ int   g_esrc[N_EDGES];
__device__ float g_enorm[N_EDGES];
__device__ float g_y   [N_NODES * HID_CH];
__device__ float g_h1  [N_NODES * HID_CH];
__device__ float g_w1t [HID_CH * KDIM];   // W1^T  [256][256] K-major
__device__ float g_w2t [OUT_CH * KDIM];   // W2^T  [128][256] K-major
__device__ int   g_is64;

__device__ __forceinline__ uint32_t f2tf32(float x) {
    uint32_t u; asm("cvt.rna.tf32.f32 %0, %1;" : "=r"(u) : "f"(x)); return u;
}

// ---------------- edge dtype detection ----------------
__global__ void k_init_flags() { g_is64 = 1; }
__global__ void k_detect(const unsigned int* __restrict__ w) {
    int i = blockIdx.x * blockDim.x + threadIdx.x;
    if (i < N_EDGES && w[2 * i + 1] != 0) g_is64 = 0;  // benign race
}
__device__ __forceinline__ int load_idx(const void* __restrict__ ei, int which, int e) {
    if (g_is64)
        return (int)((const long long*)ei)[(size_t)which * N_EDGES + e];
    return ((const int*)ei)[which * N_EDGES + e];
}

// ---------------- CSR build ----------------
__global__ void k_zero_degi() {
    int i = blockIdx.x * blockDim.x + threadIdx.x;
    if (i < N_NODES) g_degi[i] = 0;
}
__global__ void k_hist(const void* __restrict__ ei) {
    int e = blockIdx.x * blockDim.x + threadIdx.x;
    if (e < N_EDGES) atomicAdd(&g_degi[load_idx(ei, 1, e)], 1);
}
__global__ void k_scan() {
    __shared__ int part[1024];
    int tid = threadIdx.x;
    const int per = (N_NODES + 1023) / 1024;
    int start = tid * per;
    int end   = min(start + per, N_NODES);
    int s = 0;
    for (int i = start; i < end; i++) s += g_degi[i];
    part[tid] = s;
    __syncthreads();
    for (int off = 1; off < 1024; off <<= 1) {
        int v = (tid >= off) ? part[tid - off] : 0;
        __syncthreads();
        part[tid] += v;
        __syncthreads();
    }
    int run = (tid > 0) ? part[tid - 1] : 0;
    for (int i = start; i < end; i++) {
        g_off[i] = run;
        g_cur[i] = run;
        run += g_degi[i];
        g_dinv[i] = rsqrtf((float)(g_degi[i] + 1));
    }
    if (tid == 1023) g_off[N_NODES] = N_EDGES;
}
__global__ void k_fill(const void* __restrict__ ei) {
    int e = blockIdx.x * blockDim.x + threadIdx.x;
    if (e >= N_EDGES) return;
    int s = load_idx(ei, 0, e);
    int d = load_idx(ei, 1, e);
    int pos = atomicAdd(&g_cur[d], 1);
    g_esrc[pos]  = s;
    g_enorm[pos] = g_dinv[s] * g_dinv[d];
}

// ---------------- weight transpose: W[K,N] -> WT[N,K] ----------------
__global__ void k_transpose(const float* __restrict__ W, float* __restrict__ WT, int K, int N) {
    int i = blockIdx.x * blockDim.x + threadIdx.x;
    if (i < K * N) {
        int k = i / N, n = i - k * N;
        WT[n * K + k] = W[i];
    }
}

// ---------------- TF32 mma.sync GEMM: C[M,N] = A[M,256] @ BT[N,256]^T ----------------
// CTA 128x128, 8 warps (4x2), warp tile 32x64, mma.m16n8k8 tf32, K staged 32-wide.
__global__ __launch_bounds__(256) void mma_gemm(const float* __restrict__ A,
                                                const float* __restrict__ BT,
                                                float* __restrict__ C, int M, int N) {
    constexpr int KC  = 32;
    constexpr int PAD = 36;
    __shared__ uint32_t As[128 * PAD];
    __shared__ uint32_t Bs[128 * PAD];

    int tid  = threadIdx.x;
    int wid  = tid >> 5;
    int lane = tid & 31;
    int g = lane >> 2;          // 0..7
    int t = lane & 3;           // 0..3

    int rowBase = blockIdx.x * 128;
    int colBase = blockIdx.y * 128;
    int wm = wid & 3;           // 0..3 -> 32-row slice
    int wn = wid >> 2;          // 0..1 -> 64-col slice

    float acc[2][8][4];
    #pragma unroll
    for (int i = 0; i < 2; i++)
        #pragma unroll
        for (int j = 0; j < 8; j++)
            #pragma unroll
            for (int q = 0; q < 4; q++) acc[i][j][q] = 0.0f;

    for (int k0 = 0; k0 < KDIM; k0 += KC) {
        // stage A chunk: 128 rows x 32 k (tf32 bits), float4-coalesced
        #pragma unroll
        for (int it = 0; it < 4; it++) {
            int f = tid + it * 256;           // 0..1023
            int row = f >> 3;
            int c4  = (f & 7) << 2;
            int gr = rowBase + row;
            float4 v = make_float4(0.f, 0.f, 0.f, 0.f);
            if (gr < M) v = *(const float4*)&A[(size_t)gr * KDIM + k0 + c4];
            uint4 u = make_uint4(f2tf32(v.x), f2tf32(v.y), f2tf32(v.z), f2tf32(v.w));
            *(uint4*)&As[row * PAD + c4] = u;
        }
        // stage B chunk: 128 n-rows x 32 k (BT is [N][K])
        #pragma unroll
        for (int it = 0; it < 4; it++) {
            int f = tid + it * 256;
            int n  = f >> 3;
            int c4 = (f & 7) << 2;
            float4 v = *(const float4*)&BT[(size_t)(colBase + n) * KDIM + k0 + c4];
            uint4 u = make_uint4(f2tf32(v.x), f2tf32(v.y), f2tf32(v.z), f2tf32(v.w));
            *(uint4*)&Bs[n * PAD + c4] = u;
        }
        __syncthreads();

        #pragma unroll
        for (int kk = 0; kk < KC; kk += 8) {
            // A fragments for 2 m16 tiles
            uint32_t a[2][4];
            #pragma unroll
            for (int mf = 0; mf < 2; mf++) {
                int r0 = wm * 32 + mf * 16 + g;
                a[mf][0] = As[r0 * PAD + kk + t];
                a[mf][1] = As[(r0 + 8) * PAD + kk + t];
                a[mf][2] = As[r0 * PAD + kk + t + 4];
                a[mf][3] = As[(r0 + 8) * PAD + kk + t + 4];
            }
            // B fragments for 8 n8 tiles
            uint32_t b[8][2];
            #pragma unroll
            for (int nf = 0; nf < 8; nf++) {
                int n0 = wn * 64 + nf * 8 + g;
                b[nf][0] = Bs[n0 * PAD + kk + t];
                b[nf][1] = Bs[n0 * PAD + kk + t + 4];
            }
            #pragma unroll
            for (int mf = 0; mf < 2; mf++)
                #pragma unroll
                for (int nf = 0; nf < 8; nf++) {
                    asm volatile(
                        "mma.sync.aligned.m16n8k8.row.col.f32.tf32.tf32.f32 "
                        "{%0,%1,%2,%3}, {%4,%5,%6,%7}, {%8,%9}, {%0,%1,%2,%3};"
                        : "+f"(acc[mf][nf][0]), "+f"(acc[mf][nf][1]),
                          "+f"(acc[mf][nf][2]), "+f"(acc[mf][nf][3])
                        : "r"(a[mf][0]), "r"(a[mf][1]), "r"(a[mf][2]), "r"(a[mf][3]),
                          "r"(b[nf][0]), "r"(b[nf][1]));
                }
        }
        __syncthreads();
    }

    // epilogue
    #pragma unroll
    for (int mf = 0; mf < 2; mf++) {
        int r0 = rowBase + wm * 32 + mf * 16 + g;
        #pragma unroll
        for (int nf = 0; nf < 8; nf++) {
            int c0 = colBase + wn * 64 + nf * 8 + t * 2;
            if (r0 < M)
                *(float2*)&C[(size_t)r0 * N + c0] =
                    make_float2(acc[mf][nf][0], acc[mf][nf][1]);
            if (r0 + 8 < M)
                *(float2*)&C[(size_t)(r0 + 8) * N + c0] =
                    make_float2(acc[mf][nf][2], acc[mf][nf][3]);
        }
    }
}

// ---------------- CSR gather + fused epilogue ----------------
template <int CH, bool RELU>
__global__ void k_gather(const float* __restrict__ y,
                         const float* __restrict__ b,
                         float* __restrict__ out) {
    constexpr int TPN = CH / 4;
    constexpr int NPB = 256 / TPN;
    int lane = threadIdx.x % TPN;
    int node = blockIdx.x * NPB + threadIdx.x / TPN;
    if (node >= N_NODES) return;

    int beg = g_off[node];
    int end = g_off[node + 1];

    float4 acc = make_float4(0.f, 0.f, 0.f, 0.f);
    for (int p = beg; p < end; p++) {
        int   s   = g_esrc[p];
        float nrm = g_enorm[p];
        float4 v = *(const float4*)&y[(size_t)s * CH + lane * 4];
        acc.x += v.x * nrm; acc.y += v.y * nrm;
        acc.z += v.z * nrm; acc.w += v.w * nrm;
    }

    float di = g_dinv[node];
    float w  = di * di;
    float4 self = *(const float4*)&y[(size_t)node * CH + lane * 4];
    float4 bb   = *(const float4*)&b[lane * 4];
    acc.x += self.x * w + bb.x;
    acc.y += self.y * w + bb.y;
    acc.z += self.z * w + bb.z;
    acc.w += self.w * w + bb.w;
    if (RELU) {
        acc.x = fmaxf(acc.x, 0.f); acc.y = fmaxf(acc.y, 0.f);
        acc.z = fmaxf(acc.z, 0.f); acc.w = fmaxf(acc.w, 0.f);
    }
    *(float4*)&out[(size_t)node * CH + lane * 4] = acc;
}

// ---------------- launch ----------------
extern "C" void kernel_launch(void* const* d_in, const int* in_sizes, int n_in,
                              void* d_out, int out_size) {
    const float* x   = (const float*)d_in[0];
    const void*  ei  = d_in[1];
    const float* W1  = (const float*)d_in[2];
    const float* b1  = (const float*)d_in[3];
    const float* W2  = (const float*)d_in[4];
    const float* b2  = (const float*)d_in[5];
    float*       out = (float*)d_out;

    float *p_y, *p_h1, *p_w1t, *p_w2t;
    cudaGetSymbolAddress((void**)&p_y,   g_y);
    cudaGetSymbolAddress((void**)&p_h1,  g_h1);
    cudaGetSymbolAddress((void**)&p_w1t, g_w1t);
    cudaGetSymbolAddress((void**)&p_w2t, g_w2t);

    // 0) dtype detection
    k_init_flags<<<1, 1>>>();
    k_detect<<<(N_EDGES + 255) / 256, 256>>>((const unsigned int*)ei);

    // 1) CSR build (+ dinv) and weight transposes
    k_zero_degi<<<(N_NODES + 255) / 256, 256>>>();
    k_hist<<<(N_EDGES + 255) / 256, 256>>>(ei);
    k_transpose<<<(IN_CH * HID_CH + 255) / 256, 256>>>(W1, p_w1t, IN_CH, HID_CH);
    k_transpose<<<(HID_CH * OUT_CH + 255) / 256, 256>>>(W2, p_w2t, HID_CH, OUT_CH);
    k_scan<<<1, 1024>>>();
    k_fill<<<(N_EDGES + 255) / 256, 256>>>(ei);

    const int MT = (N_NODES + 127) / 128;  // 157 row tiles

    // 2) layer 1: y = x @ W1 (tf32 mma) ; h1 = relu(gather(y) + self + b1)
    {
        dim3 grid(MT, HID_CH / 128);
        mma_gemm<<<grid, 256>>>(x, p_w1t, p_y, N_NODES, HID_CH);
    }
    {
        constexpr int NPB = 256 / (HID_CH / 4);
        k_gather<HID_CH, true><<<(N_NODES + NPB - 1) / NPB, 256>>>(p_y, b1, p_h1);
    }

    // 3) layer 2: y = h1 @ W2 ; out = gather(y) + self + b2
    {
        dim3 grid(MT, OUT_CH / 128);
        mma_gemm<<<grid, 256>>>(p_h1, p_w2t, p_y, N_NODES, OUT_CH);
    }
    {
        constexpr int NPB = 256 / (OUT_CH / 4);
        k_gather<OUT_CH, false><<<(N_NODES + NPB - 1) / NPB, 256>>>(p_y, b2, out);
    }
}